// round 1
// baseline (speedup 1.0000x reference)
#include <cuda_runtime.h>
#include <math.h>

#define Nn 64
#define Cdim 128
#define Pdim 4096
#define Kdim 64
#define PSPLIT 8

// ---- device scratch (static globals: allowed; no runtime allocation) ----
__device__ float g_inv[Nn * Pdim];                                   // 1 MB
__device__ float g_a[(size_t)Nn * Kdim * Pdim];                      // 64 MB  (a * inv_norm)
__device__ float g_asum[Nn * Kdim];                                  // 16 KB  (sum_p a)
__device__ float g_vpart[(size_t)Nn * PSPLIT * Kdim * Cdim];         // 16 MB  (partial vlad)

// ---- packed f32x2 helpers (Blackwell dual-FP32 path) ----
__device__ __forceinline__ void fma2(unsigned long long& d, unsigned long long a, unsigned long long b) {
    asm("fma.rn.f32x2 %0, %1, %2, %0;" : "+l"(d) : "l"(a), "l"(b));
}
__device__ __forceinline__ unsigned long long pack2(float v) {
    unsigned long long r;
    unsigned u = __float_as_uint(v);
    asm("mov.b64 %0, {%1, %2};" : "=l"(r) : "r"(u), "r"(u));
    return r;
}

// =====================================================================
// K_zero: zero the asum accumulator
// =====================================================================
__global__ void k_zero() {
    int i = blockIdx.x * 256 + threadIdx.x;
    if (i < Nn * Kdim) g_asum[i] = 0.0f;
}

// =====================================================================
// K_inv: inv_norm[n][p] = 1 / max(||x[n,:,p]||_2, eps)
// 4 pixels per thread via float4, fully coalesced over p.
// =====================================================================
__global__ __launch_bounds__(256) void k_inv(const float* __restrict__ x) {
    int gid = blockIdx.x * 256 + threadIdx.x;   // 65536 threads total
    int n = gid >> 10;                           // 1024 threads per image
    int p4 = (gid & 1023) << 2;
    const float* xb = x + (size_t)n * Cdim * Pdim + p4;
    float sx = 0.f, sy = 0.f, sz = 0.f, sw = 0.f;
#pragma unroll 8
    for (int c = 0; c < Cdim; ++c) {
        float4 v = *(const float4*)(xb + (size_t)c * Pdim);
        sx += v.x * v.x; sy += v.y * v.y; sz += v.z * v.z; sw += v.w * v.w;
    }
    float4 o;
    o.x = 1.f / fmaxf(sqrtf(sx), 1e-12f);
    o.y = 1.f / fmaxf(sqrtf(sy), 1e-12f);
    o.z = 1.f / fmaxf(sqrtf(sz), 1e-12f);
    o.w = 1.f / fmaxf(sqrtf(sw), 1e-12f);
    *(float4*)(g_inv + (size_t)n * Pdim + p4) = o;
}

// =====================================================================
// K_logits: per (n, 256-pixel tile):
//   logits[k,p] = inv[p] * (W @ x_raw)[k,p] + b[k]   (fp32 GEMM, f32x2 packed)
//   a = softmax_k(logits);  write a*inv to g_a;  accumulate asum.
// Block 256 threads; thread (i=tid&7, j=tid>>3) owns 8k x 8p outputs.
// =====================================================================
__global__ __launch_bounds__(256, 2) void k_logits(const float* __restrict__ x,
                                                   const float* __restrict__ conv_w,
                                                   const float* __restrict__ conv_b) {
    const int n = blockIdx.y;
    const int p0 = blockIdx.x * 256;
    const int tid = threadIdx.x;
    const int i = tid & 7, j = tid >> 3;
    const int i8 = i * 8, j8 = j * 8;

    __shared__ __align__(16) float w_s[128 * 68];   // [c][k], padded row 68
    __shared__ __align__(16) float xred[8 * 256];   // x chunk during GEMM; red buffer after
    __shared__ float s_asum[64];

    // load conv_w transposed: w_s[c*68 + k]
#pragma unroll
    for (int m = 0; m < 32; ++m) {
        int idx = tid + m * 256;
        int k = idx >> 7, c = idx & 127;
        w_s[c * 68 + k] = conv_w[idx];
    }
    if (tid < 64) s_asum[tid] = 0.0f;

    unsigned long long acc[8][4];
#pragma unroll
    for (int a = 0; a < 8; ++a)
#pragma unroll
        for (int b = 0; b < 4; ++b) acc[a][b] = 0ull;

    const float* xg = x + (size_t)n * Cdim * Pdim + p0;

    for (int cb = 0; cb < 128; cb += 8) {
        __syncthreads();
        {
            int r = tid >> 5, lane = tid & 31;
            const float4* src = (const float4*)(xg + (size_t)(cb + r) * Pdim);
            float4 v0 = src[lane];
            float4 v1 = src[lane + 32];
            *(float4*)&xred[r * 256 + lane * 4] = v0;
            *(float4*)&xred[r * 256 + 128 + lane * 4] = v1;
        }
        __syncthreads();
#pragma unroll
        for (int cc = 0; cc < 8; ++cc) {
            int c = cb + cc;
            float4 w0 = *(const float4*)&w_s[c * 68 + i8];
            float4 w1 = *(const float4*)&w_s[c * 68 + i8 + 4];
            ulonglong2 x0 = *(const ulonglong2*)&xred[cc * 256 + j8];
            ulonglong2 x1 = *(const ulonglong2*)&xred[cc * 256 + j8 + 4];
            unsigned long long wb[8];
            wb[0] = pack2(w0.x); wb[1] = pack2(w0.y); wb[2] = pack2(w0.z); wb[3] = pack2(w0.w);
            wb[4] = pack2(w1.x); wb[5] = pack2(w1.y); wb[6] = pack2(w1.z); wb[7] = pack2(w1.w);
#pragma unroll
            for (int kk = 0; kk < 8; ++kk) {
                fma2(acc[kk][0], wb[kk], x0.x);
                fma2(acc[kk][1], wb[kk], x0.y);
                fma2(acc[kk][2], wb[kk], x1.x);
                fma2(acc[kk][3], wb[kk], x1.y);
            }
        }
    }
    __syncthreads();   // xred now reused as reduction buffer

    // finalize logits: l = inv[p]*dot + b[k]
    float iv[8];
    {
        const float4* ivp = (const float4*)(g_inv + (size_t)n * Pdim + p0 + j8);
        float4 a0 = ivp[0], a1 = ivp[1];
        iv[0] = a0.x; iv[1] = a0.y; iv[2] = a0.z; iv[3] = a0.w;
        iv[4] = a1.x; iv[5] = a1.y; iv[6] = a1.z; iv[7] = a1.w;
    }
    float b8[8];
#pragma unroll
    for (int kk = 0; kk < 8; ++kk) b8[kk] = conv_b[i8 + kk];

    float l[8][8];
#pragma unroll
    for (int kk = 0; kk < 8; ++kk) {
#pragma unroll
        for (int pp = 0; pp < 4; ++pp) {
            float2 d = *(float2*)&acc[kk][pp];
            l[kk][2 * pp]     = d.x * iv[2 * pp] + b8[kk];
            l[kk][2 * pp + 1] = d.y * iv[2 * pp + 1] + b8[kk];
        }
    }

    // softmax over k (64 values per pixel, split across 8 i-threads)
    float m8[8];
#pragma unroll
    for (int pi = 0; pi < 8; ++pi) {
        float m = l[0][pi];
#pragma unroll
        for (int kk = 1; kk < 8; ++kk) m = fmaxf(m, l[kk][pi]);
        m8[pi] = m;
    }
#pragma unroll
    for (int pi = 0; pi < 8; ++pi) xred[i * 256 + j8 + pi] = m8[pi];
    __syncthreads();
    float gm[8];
#pragma unroll
    for (int pi = 0; pi < 8; ++pi) {
        float m = -1e30f;
#pragma unroll
        for (int ii = 0; ii < 8; ++ii) m = fmaxf(m, xred[ii * 256 + j8 + pi]);
        gm[pi] = m;
    }
    __syncthreads();
    float s8[8] = {0, 0, 0, 0, 0, 0, 0, 0};
#pragma unroll
    for (int kk = 0; kk < 8; ++kk) {
#pragma unroll
        for (int pi = 0; pi < 8; ++pi) {
            float e = __expf(l[kk][pi] - gm[pi]);
            l[kk][pi] = e;
            s8[pi] += e;
        }
    }
#pragma unroll
    for (int pi = 0; pi < 8; ++pi) xred[i * 256 + j8 + pi] = s8[pi];
    __syncthreads();
    float r8[8];
#pragma unroll
    for (int pi = 0; pi < 8; ++pi) {
        float s = 0.f;
#pragma unroll
        for (int ii = 0; ii < 8; ++ii) s += xred[ii * 256 + j8 + pi];
        r8[pi] = 1.f / s;
    }

    // a = l*r8; asum += a; write a*inv to g_a
    float* ga = g_a + (size_t)(n * Kdim) * Pdim + p0 + j8;
#pragma unroll
    for (int kk = 0; kk < 8; ++kk) {
        float av[8];
        float sk = 0.f;
#pragma unroll
        for (int pi = 0; pi < 8; ++pi) {
            float a = l[kk][pi] * r8[pi];
            sk += a;
            av[pi] = a * iv[pi];
        }
        sk += __shfl_xor_sync(0xffffffffu, sk, 8);
        sk += __shfl_xor_sync(0xffffffffu, sk, 16);
        if ((tid & 31) < 8) atomicAdd(&s_asum[i8 + kk], sk);
        float* row = ga + (size_t)(i8 + kk) * Pdim;
        *(float4*)row       = make_float4(av[0], av[1], av[2], av[3]);
        *(float4*)(row + 4) = make_float4(av[4], av[5], av[6], av[7]);
    }
    __syncthreads();
    if (tid < 64) atomicAdd(&g_asum[n * Kdim + tid], s_asum[tid]);
}

// =====================================================================
// K_vlad: partial vlad GEMM. vpart[n][ps][k][c] = sum_{p in split} a'[k,p]*x[c,p]
// Block 128 threads; thread (i=tid&7, j=tid>>3) owns 8k x 8c outputs.
// =====================================================================
__global__ __launch_bounds__(128, 4) void k_vlad(const float* __restrict__ x) {
    const int n = blockIdx.y, ps = blockIdx.x;
    const int tid = threadIdx.x;
    const int i = tid & 7, j = tid >> 3;     // j in 0..15
    const int i8 = i * 8, j8 = j * 8;

    __shared__ __align__(16) float a_s[32 * 68];    // [p][k], pad 68
    __shared__ __align__(16) float x_s[32 * 132];   // [p][c], pad 132

    unsigned long long acc[8][4];
#pragma unroll
    for (int a = 0; a < 8; ++a)
#pragma unroll
        for (int b = 0; b < 4; ++b) acc[a][b] = 0ull;

    const float* ga = g_a + (size_t)(n * Kdim) * Pdim + ps * 512;
    const float* xg = x + (size_t)n * Cdim * Pdim + ps * 512;

    for (int pb = 0; pb < 512; pb += 32) {
        __syncthreads();
#pragma unroll
        for (int m = 0; m < 16; ++m) {                     // a chunk: 64k x 32p
            int idx = tid + m * 128;
            int k = idx >> 5, pc = idx & 31;
            a_s[pc * 68 + k] = ga[(size_t)k * Pdim + pb + pc];
        }
#pragma unroll
        for (int m = 0; m < 32; ++m) {                     // x chunk: 128c x 32p
            int idx = tid + m * 128;
            int c = idx >> 5, pc = idx & 31;
            x_s[pc * 132 + c] = xg[(size_t)c * Pdim + pb + pc];
        }
        __syncthreads();
#pragma unroll 8
        for (int pc = 0; pc < 32; ++pc) {
            float4 a0 = *(const float4*)&a_s[pc * 68 + i8];
            float4 a1 = *(const float4*)&a_s[pc * 68 + i8 + 4];
            ulonglong2 x0 = *(const ulonglong2*)&x_s[pc * 132 + j8];
            ulonglong2 x1 = *(const ulonglong2*)&x_s[pc * 132 + j8 + 4];
            unsigned long long ab[8];
            ab[0] = pack2(a0.x); ab[1] = pack2(a0.y); ab[2] = pack2(a0.z); ab[3] = pack2(a0.w);
            ab[4] = pack2(a1.x); ab[5] = pack2(a1.y); ab[6] = pack2(a1.z); ab[7] = pack2(a1.w);
#pragma unroll
            for (int kk = 0; kk < 8; ++kk) {
                fma2(acc[kk][0], ab[kk], x0.x);
                fma2(acc[kk][1], ab[kk], x0.y);
                fma2(acc[kk][2], ab[kk], x1.x);
                fma2(acc[kk][3], ab[kk], x1.y);
            }
        }
    }

    float* vp = g_vpart + ((size_t)(n * PSPLIT + ps) * Kdim + i8) * Cdim + j8;
#pragma unroll
    for (int kk = 0; kk < 8; ++kk) {
        union { unsigned long long u[4]; float4 v[2]; } t;
        t.u[0] = acc[kk][0]; t.u[1] = acc[kk][1]; t.u[2] = acc[kk][2]; t.u[3] = acc[kk][3];
        float* row = vp + (size_t)kk * Cdim;
        *(float4*)row       = t.v[0];
        *(float4*)(row + 4) = t.v[1];
    }
}

// =====================================================================
// K_final: per n: reduce partials, subtract asum*centroid, intra-norm
// per (k) row, global L2 norm, write output.
// =====================================================================
__global__ __launch_bounds__(256) void k_final(const float* __restrict__ cent,
                                               float* __restrict__ out) {
    const int n = blockIdx.x;
    const int tid = threadIdx.x;
    __shared__ float vl[Kdim * Cdim];    // 32 KB
    __shared__ float rn[Kdim];
    __shared__ float redb[8];
    __shared__ float gscale;

    for (int idx = tid; idx < Kdim * Cdim; idx += 256) {
        float s = 0.f;
#pragma unroll
        for (int ps = 0; ps < PSPLIT; ++ps)
            s += g_vpart[(size_t)(n * PSPLIT + ps) * (Kdim * Cdim) + idx];
        int k = idx >> 7;
        s -= g_asum[n * Kdim + k] * cent[idx];
        vl[idx] = s;
    }
    __syncthreads();

    int w = tid >> 5, lane = tid & 31;
    for (int k = w; k < Kdim; k += 8) {
        float t = 0.f;
#pragma unroll
        for (int m = 0; m < 4; ++m) {
            float v = vl[k * 128 + lane + m * 32];
            t += v * v;
        }
#pragma unroll
        for (int off = 16; off > 0; off >>= 1) t += __shfl_xor_sync(0xffffffffu, t, off);
        if (lane == 0) rn[k] = 1.f / fmaxf(sqrtf(t), 1e-12f);
    }
    __syncthreads();

    float tot = 0.f;
    for (int idx = tid; idx < Kdim * Cdim; idx += 256) {
        float v = vl[idx] * rn[idx >> 7];
        vl[idx] = v;
        tot += v * v;
    }
#pragma unroll
    for (int off = 16; off > 0; off >>= 1) tot += __shfl_xor_sync(0xffffffffu, tot, off);
    if (lane == 0) redb[w] = tot;
    __syncthreads();
    if (tid == 0) {
        float t = 0.f;
#pragma unroll
        for (int q = 0; q < 8; ++q) t += redb[q];
        gscale = 1.f / fmaxf(sqrtf(t), 1e-12f);
    }
    __syncthreads();
    float gs = gscale;
    for (int idx = tid; idx < Kdim * Cdim; idx += 256)
        out[(size_t)n * (Kdim * Cdim) + idx] = vl[idx] * gs;
}

// =====================================================================
extern "C" void kernel_launch(void* const* d_in, const int* in_sizes, int n_in,
                              void* d_out, int out_size) {
    const float* x      = (const float*)d_in[0];   // [64,128,64,64]
    // d_in[1] = xyz (unused by reference)
    const float* cent   = (const float*)d_in[2];   // [64,128]
    const float* conv_w = (const float*)d_in[3];   // [64,128]
    const float* conv_b = (const float*)d_in[4];   // [64]
    float* out = (float*)d_out;                    // [64, 8192, 1]

    k_zero<<<16, 256>>>();
    k_inv<<<256, 256>>>(x);
    k_logits<<<dim3(16, 64), 256>>>(x, conv_w, conv_b);
    k_vlad<<<dim3(PSPLIT, 64), 128>>>(x);
    k_final<<<64, 256>>>(cent, out);
}

// round 3
// speedup vs baseline: 2.3544x; 2.3544x over previous
#include <cuda_runtime.h>
#include <cuda_bf16.h>
#include <cstdint>
#include <math.h>

#define Nn 64
#define Cdim 128
#define Pdim 4096
#define Kdim 64
#define PSPLIT 4

// ---- device scratch ----
__device__ __nv_bfloat16 g_a[(size_t)Nn * Kdim * Pdim];     // 32 MB  (a * inv_norm, bf16)
__device__ float g_asum[Nn * Kdim];                          // 16 KB  (exact fp32 sum_p a)
__device__ float g_vpart[(size_t)Nn * PSPLIT * Cdim * Kdim]; // 8 MB   [n][ps][c][k]

// ---- mma / ldmatrix wrappers (baseline PTX, sm_80+, valid on sm_103) ----
__device__ __forceinline__ uint32_t smem_u32(const void* p) {
    uint32_t a;
    asm("{ .reg .u64 t; cvta.to.shared.u64 t, %1; cvt.u32.u64 %0, t; }" : "=r"(a) : "l"(p));
    return a;
}
__device__ __forceinline__ void ldsm_x4(uint32_t* r, uint32_t addr) {
    asm volatile("ldmatrix.sync.aligned.m8n8.x4.shared.b16 {%0,%1,%2,%3}, [%4];"
                 : "=r"(r[0]), "=r"(r[1]), "=r"(r[2]), "=r"(r[3]) : "r"(addr));
}
__device__ __forceinline__ void ldsm_x2_trans(uint32_t* r, uint32_t addr) {
    asm volatile("ldmatrix.sync.aligned.m8n8.x2.trans.shared.b16 {%0,%1}, [%2];"
                 : "=r"(r[0]), "=r"(r[1]) : "r"(addr));
}
__device__ __forceinline__ void mma_bf16(float* d, const uint32_t* a, const uint32_t* b) {
    asm volatile(
        "mma.sync.aligned.m16n8k16.row.col.f32.bf16.bf16.f32 "
        "{%0,%1,%2,%3}, {%4,%5,%6,%7}, {%8,%9}, {%0,%1,%2,%3};"
        : "+f"(d[0]), "+f"(d[1]), "+f"(d[2]), "+f"(d[3])
        : "r"(a[0]), "r"(a[1]), "r"(a[2]), "r"(a[3]), "r"(b[0]), "r"(b[1]));
}
__device__ __forceinline__ void split_bf16(float v, __nv_bfloat16& h, __nv_bfloat16& l) {
    h = __float2bfloat16(v);
    l = __float2bfloat16(v - __bfloat162float(h));
}

// =====================================================================
__global__ void k_zero() {
    int i = blockIdx.x * 256 + threadIdx.x;
    if (i < Nn * Kdim) g_asum[i] = 0.0f;
}

// =====================================================================
// K_logits_mma: per (n, 256-pixel tile).
//  - stage raw x in 32-channel chunks as bf16 hi/lo; accumulate sumsq per pixel
//  - logits = inv * (W @ x) + b via 3-term bf16 mma split
//  - softmax over 64 clusters; write a*inv (bf16) to g_a; exact fp32 asum.
// Dynamic smem 70144 B.
// =====================================================================
#define L_WN 8704    // 64*136 elems per W plane
#define L_XN 8448    // 32*264 elems per x plane
#define L_SMEM 70144

__global__ __launch_bounds__(256, 2) void k_logits_mma(const float* __restrict__ x,
                                                       const float* __restrict__ conv_w,
                                                       const float* __restrict__ conv_b) {
    extern __shared__ __align__(16) char dsm[];
    __nv_bfloat16* wh = (__nv_bfloat16*)dsm;
    __nv_bfloat16* wl = wh + L_WN;
    __nv_bfloat16* xh = wl + L_WN;
    __nv_bfloat16* xl = xh + L_XN;
    __nv_bfloat16* aout = xh;                  // alias: 64*264 == 2*32*264
    float* s_sumsq = (float*)(xl + L_XN);      // 256
    float* s_asum = s_sumsq + 256;             // 64
    float* s_b = s_asum + 64;                  // 64

    const int n = blockIdx.y;
    const int p0 = blockIdx.x * 256;
    const int tid = threadIdx.x;
    const int w = tid >> 5, lane = tid & 31;
    const int pw = w * 32;                     // warp's p-col base within tile

    const uint32_t u_wh = smem_u32(wh), u_wl = smem_u32(wl);
    const uint32_t u_xh = smem_u32(xh), u_xl = smem_u32(xl);

    // stage W hi/lo (whole 64x128), b, init reductions
#pragma unroll
    for (int r = 0; r < 8; ++r) {
        int f4 = tid + r * 256;
        int row = f4 >> 5, col4 = f4 & 31;
        float4 v = *(const float4*)(conv_w + row * 128 + col4 * 4);
        __nv_bfloat16 h, l;
        split_bf16(v.x, h, l); wh[row * 136 + col4 * 4 + 0] = h; wl[row * 136 + col4 * 4 + 0] = l;
        split_bf16(v.y, h, l); wh[row * 136 + col4 * 4 + 1] = h; wl[row * 136 + col4 * 4 + 1] = l;
        split_bf16(v.z, h, l); wh[row * 136 + col4 * 4 + 2] = h; wl[row * 136 + col4 * 4 + 2] = l;
        split_bf16(v.w, h, l); wh[row * 136 + col4 * 4 + 3] = h; wl[row * 136 + col4 * 4 + 3] = l;
    }
    if (tid < 64) { s_b[tid] = conv_b[tid]; s_asum[tid] = 0.f; }
    s_sumsq[tid] = 0.f;

    float acc[4][4][4];
#pragma unroll
    for (int a = 0; a < 4; ++a)
#pragma unroll
        for (int b = 0; b < 4; ++b)
#pragma unroll
            for (int c = 0; c < 4; ++c) acc[a][b][c] = 0.f;

    const float* xg = x + (size_t)n * Cdim * Pdim + p0;

    for (int cb = 0; cb < 128; cb += 32) {
        __syncthreads();
        // stage x chunk [32c][256p] -> bf16 hi/lo
#pragma unroll
        for (int r = 0; r < 8; ++r) {
            int f4 = tid + r * 256;
            int row = f4 >> 6, col4 = f4 & 63;
            float4 v = *(const float4*)(xg + (size_t)(cb + row) * Pdim + col4 * 4);
            __nv_bfloat16 h, l;
            split_bf16(v.x, h, l); xh[row * 264 + col4 * 4 + 0] = h; xl[row * 264 + col4 * 4 + 0] = l;
            split_bf16(v.y, h, l); xh[row * 264 + col4 * 4 + 1] = h; xl[row * 264 + col4 * 4 + 1] = l;
            split_bf16(v.z, h, l); xh[row * 264 + col4 * 4 + 2] = h; xl[row * 264 + col4 * 4 + 2] = l;
            split_bf16(v.w, h, l); xh[row * 264 + col4 * 4 + 3] = h; xl[row * 264 + col4 * 4 + 3] = l;
        }
        __syncthreads();
        // sumsq for this pixel (tid == p index)
        {
            float ss = 0.f;
#pragma unroll
            for (int c = 0; c < 32; ++c) {
                float v = __bfloat162float(xh[c * 264 + tid]) + __bfloat162float(xl[c * 264 + tid]);
                ss += v * v;
            }
            s_sumsq[tid] += ss;
        }
        // mma: 2 k16 steps
#pragma unroll
        for (int ks = 0; ks < 2; ++ks) {
            uint32_t bh[4][2], bl[4][2];
#pragma unroll
            for (int nt = 0; nt < 4; ++nt) {
                uint32_t off = (uint32_t)(((ks * 16 + (lane & 15)) * 264 + pw + nt * 8) * 2);
                ldsm_x2_trans(bh[nt], u_xh + off);
                ldsm_x2_trans(bl[nt], u_xl + off);
            }
#pragma unroll
            for (int mt = 0; mt < 4; ++mt) {
                uint32_t ah[4], al[4];
                uint32_t off = (uint32_t)(((mt * 16 + (lane & 15)) * 136 + cb + ks * 16 + (lane >> 4) * 8) * 2);
                ldsm_x4(ah, u_wh + off);
                ldsm_x4(al, u_wl + off);
#pragma unroll
                for (int nt = 0; nt < 4; ++nt) {
                    mma_bf16(acc[mt][nt], ah, bh[nt]);
                    mma_bf16(acc[mt][nt], ah, bl[nt]);
                    mma_bf16(acc[mt][nt], al, bh[nt]);
                }
            }
        }
    }
    __syncthreads();
    s_sumsq[tid] = 1.f / fmaxf(sqrtf(s_sumsq[tid]), 1e-12f);   // -> inv in place
    __syncthreads();
    float* s_inv = s_sumsq;

    // epilogue: logits -> softmax -> a*inv (bf16) + exact asum
    float iv0[4], iv1[4];
#pragma unroll
    for (int nt = 0; nt < 4; ++nt) {
        int c0 = pw + nt * 8 + (lane & 3) * 2;
        iv0[nt] = s_inv[c0];
        iv1[nt] = s_inv[c0 + 1];
    }
    float bb0[4], bb1[4];
#pragma unroll
    for (int mt = 0; mt < 4; ++mt) {
        bb0[mt] = s_b[mt * 16 + (lane >> 2)];
        bb1[mt] = s_b[mt * 16 + (lane >> 2) + 8];
    }
    float l[4][4][4];
#pragma unroll
    for (int mt = 0; mt < 4; ++mt)
#pragma unroll
        for (int nt = 0; nt < 4; ++nt) {
            l[mt][nt][0] = acc[mt][nt][0] * iv0[nt] + bb0[mt];
            l[mt][nt][1] = acc[mt][nt][1] * iv1[nt] + bb0[mt];
            l[mt][nt][2] = acc[mt][nt][2] * iv0[nt] + bb1[mt];
            l[mt][nt][3] = acc[mt][nt][3] * iv1[nt] + bb1[mt];
        }
    // per-column max over 64 rows (8 thread-local + shfl over lane>>2 groups)
    float mx0[4], mx1[4];
#pragma unroll
    for (int nt = 0; nt < 4; ++nt) {
        float m0 = -1e30f, m1 = -1e30f;
#pragma unroll
        for (int mt = 0; mt < 4; ++mt) {
            m0 = fmaxf(m0, fmaxf(l[mt][nt][0], l[mt][nt][2]));
            m1 = fmaxf(m1, fmaxf(l[mt][nt][1], l[mt][nt][3]));
        }
#pragma unroll
        for (int s = 4; s < 32; s <<= 1) {
            m0 = fmaxf(m0, __shfl_xor_sync(0xffffffffu, m0, s));
            m1 = fmaxf(m1, __shfl_xor_sync(0xffffffffu, m1, s));
        }
        mx0[nt] = m0; mx1[nt] = m1;
    }
    // exp + column sums
    float sm0[4], sm1[4];
#pragma unroll
    for (int nt = 0; nt < 4; ++nt) {
        float s0 = 0.f, s1 = 0.f;
#pragma unroll
        for (int mt = 0; mt < 4; ++mt) {
            l[mt][nt][0] = __expf(l[mt][nt][0] - mx0[nt]); s0 += l[mt][nt][0];
            l[mt][nt][2] = __expf(l[mt][nt][2] - mx0[nt]); s0 += l[mt][nt][2];
            l[mt][nt][1] = __expf(l[mt][nt][1] - mx1[nt]); s1 += l[mt][nt][1];
            l[mt][nt][3] = __expf(l[mt][nt][3] - mx1[nt]); s1 += l[mt][nt][3];
        }
#pragma unroll
        for (int s = 4; s < 32; s <<= 1) {
            s0 += __shfl_xor_sync(0xffffffffu, s0, s);
            s1 += __shfl_xor_sync(0xffffffffu, s1, s);
        }
        sm0[nt] = 1.f / s0; sm1[nt] = 1.f / s1;
    }
    // a = e/s ; asum row partials ; a*inv -> aout smem (bf16)
    float srow0[4] = {0, 0, 0, 0}, srow1[4] = {0, 0, 0, 0};
#pragma unroll
    for (int mt = 0; mt < 4; ++mt) {
        int r0 = mt * 16 + (lane >> 2);
#pragma unroll
        for (int nt = 0; nt < 4; ++nt) {
            int c0 = pw + nt * 8 + (lane & 3) * 2;
            float a0 = l[mt][nt][0] * sm0[nt];
            float a1 = l[mt][nt][1] * sm1[nt];
            float a2 = l[mt][nt][2] * sm0[nt];
            float a3 = l[mt][nt][3] * sm1[nt];
            srow0[mt] += a0 + a1;
            srow1[mt] += a2 + a3;
            __nv_bfloat162 t0(__float2bfloat16(a0 * iv0[nt]), __float2bfloat16(a1 * iv1[nt]));
            __nv_bfloat162 t1(__float2bfloat16(a2 * iv0[nt]), __float2bfloat16(a3 * iv1[nt]));
            *(__nv_bfloat162*)&aout[r0 * 264 + c0] = t0;
            *(__nv_bfloat162*)&aout[(r0 + 8) * 264 + c0] = t1;
        }
    }
#pragma unroll
    for (int mt = 0; mt < 4; ++mt) {
        float t0 = srow0[mt], t1 = srow1[mt];
        t0 += __shfl_xor_sync(0xffffffffu, t0, 1); t0 += __shfl_xor_sync(0xffffffffu, t0, 2);
        t1 += __shfl_xor_sync(0xffffffffu, t1, 1); t1 += __shfl_xor_sync(0xffffffffu, t1, 2);
        if ((lane & 3) == 0) {
            atomicAdd(&s_asum[mt * 16 + (lane >> 2)], t0);
            atomicAdd(&s_asum[mt * 16 + (lane >> 2) + 8], t1);
        }
    }
    __syncthreads();
    // coalesced write aout -> g_a
    __nv_bfloat16* ga = g_a + (size_t)(n * Kdim) * Pdim + p0;
#pragma unroll
    for (int r = 0; r < 8; ++r) {
        int f = tid + r * 256;
        int row = f >> 5, seg = f & 31;
        *(uint4*)(ga + (size_t)row * Pdim + seg * 8) = *(uint4*)&aout[row * 264 + seg * 8];
    }
    if (tid < 64) atomicAdd(&g_asum[n * Kdim + tid], s_asum[tid]);
}

// =====================================================================
// K_vlad_mma: vpart[n][ps][c][k] = sum_{p in split} x[c,p] * a'[k,p]
// M=128(c) x N=64(k), K=1024 p per CTA; x bf16 hi/lo (2-term), a single bf16.
// =====================================================================
__global__ __launch_bounds__(256, 2) void k_vlad_mma(const float* __restrict__ x) {
    __shared__ __align__(16) __nv_bfloat16 xh[128 * 72];
    __shared__ __align__(16) __nv_bfloat16 xl[128 * 72];
    __shared__ __align__(16) __nv_bfloat16 as_[64 * 72];

    const int n = blockIdx.y, ps = blockIdx.x;
    const int tid = threadIdx.x;
    const int w = tid >> 5, lane = tid & 31;
    const int pb0 = ps * (Pdim / PSPLIT);

    const uint32_t u_xh = smem_u32(xh), u_xl = smem_u32(xl), u_as = smem_u32(as_);

    float acc[8][4];
#pragma unroll
    for (int a = 0; a < 8; ++a)
#pragma unroll
        for (int b = 0; b < 4; ++b) acc[a][b] = 0.f;

    const float* xg = x + (size_t)n * Cdim * Pdim;
    const __nv_bfloat16* ga = g_a + (size_t)(n * Kdim) * Pdim;

    for (int pc = 0; pc < (Pdim / PSPLIT) / 64; ++pc) {
        const int pb = pb0 + pc * 64;
        __syncthreads();
#pragma unroll
        for (int r = 0; r < 8; ++r) {
            int f4 = tid + r * 256;
            int row = f4 >> 4, col4 = f4 & 15;
            float4 v = *(const float4*)(xg + (size_t)row * Pdim + pb + col4 * 4);
            __nv_bfloat16 h, l;
            split_bf16(v.x, h, l); xh[row * 72 + col4 * 4 + 0] = h; xl[row * 72 + col4 * 4 + 0] = l;
            split_bf16(v.y, h, l); xh[row * 72 + col4 * 4 + 1] = h; xl[row * 72 + col4 * 4 + 1] = l;
            split_bf16(v.z, h, l); xh[row * 72 + col4 * 4 + 2] = h; xl[row * 72 + col4 * 4 + 2] = l;
            split_bf16(v.w, h, l); xh[row * 72 + col4 * 4 + 3] = h; xl[row * 72 + col4 * 4 + 3] = l;
        }
#pragma unroll
        for (int r = 0; r < 2; ++r) {
            int f = tid + r * 256;
            int row = f >> 3, seg = f & 7;
            *(uint4*)&as_[row * 72 + seg * 8] = *(const uint4*)(ga + (size_t)row * Pdim + pb + seg * 8);
        }
        __syncthreads();
#pragma unroll
        for (int ks = 0; ks < 4; ++ks) {
            uint32_t ah[4], al[4];
            uint32_t offA = (uint32_t)(((w * 16 + (lane & 15)) * 72 + ks * 16 + (lane >> 4) * 8) * 2);
            ldsm_x4(ah, u_xh + offA);
            ldsm_x4(al, u_xl + offA);
#pragma unroll
            for (int ntp = 0; ntp < 4; ++ntp) {
                uint32_t b4[4];
                int row = ntp * 16 + ((lane >> 4) << 3) + (lane & 7);
                int col = ks * 16 + ((lane >> 3) & 1) * 8;
                ldsm_x4(b4, u_as + (uint32_t)((row * 72 + col) * 2));
                mma_bf16(acc[2 * ntp], ah, b4);
                mma_bf16(acc[2 * ntp], al, b4);
                mma_bf16(acc[2 * ntp + 1], ah, b4 + 2);
                mma_bf16(acc[2 * ntp + 1], al, b4 + 2);
            }
        }
    }
    float* vp = g_vpart + (size_t)(n * PSPLIT + ps) * (Cdim * Kdim);
    int r0 = w * 16 + (lane >> 2);
    int c0 = (lane & 3) * 2;
#pragma unroll
    for (int nt = 0; nt < 8; ++nt) {
        float2 t0 = make_float2(acc[nt][0], acc[nt][1]);
        float2 t1 = make_float2(acc[nt][2], acc[nt][3]);
        *(float2*)&vp[(size_t)r0 * Kdim + nt * 8 + c0] = t0;
        *(float2*)&vp[(size_t)(r0 + 8) * Kdim + nt * 8 + c0] = t1;
    }
}

// =====================================================================
// K_final: reduce partials [n][ps][c][k], subtract asum*cent, intra + global norm.
// =====================================================================
__global__ __launch_bounds__(256) void k_final(const float* __restrict__ cent,
                                               float* __restrict__ out) {
    const int n = blockIdx.x;
    const int tid = threadIdx.x;
    __shared__ float vl[Kdim * 129];
    __shared__ float rn[Kdim];
    __shared__ float redb[8];
    __shared__ float gscale;

    const float* vp = g_vpart + (size_t)(n * PSPLIT) * (Cdim * Kdim);
    for (int idx = tid; idx < Cdim * Kdim; idx += 256) {
        float s = 0.f;
#pragma unroll
        for (int ps = 0; ps < PSPLIT; ++ps) s += vp[(size_t)ps * (Cdim * Kdim) + idx];
        int c = idx >> 6, k = idx & 63;
        s -= g_asum[n * Kdim + k] * cent[k * Cdim + c];
        vl[k * 129 + c] = s;
    }
    __syncthreads();

    int w = tid >> 5, lane = tid & 31;
    for (int k = w; k < Kdim; k += 8) {
        float t = 0.f;
#pragma unroll
        for (int m = 0; m < 4; ++m) {
            float v = vl[k * 129 + lane + m * 32];
            t += v * v;
        }
#pragma unroll
        for (int off = 16; off > 0; off >>= 1) t += __shfl_xor_sync(0xffffffffu, t, off);
        if (lane == 0) rn[k] = 1.f / fmaxf(sqrtf(t), 1e-12f);
    }
    __syncthreads();

    float tot = 0.f;
    for (int idx = tid; idx < Kdim * Cdim; idx += 256) {
        int k = idx >> 7, c = idx & 127;
        float v = vl[k * 129 + c] * rn[k];
        vl[k * 129 + c] = v;
        tot += v * v;
    }
#pragma unroll
    for (int off = 16; off > 0; off >>= 1) tot += __shfl_xor_sync(0xffffffffu, tot, off);
    if (lane == 0) redb[w] = tot;
    __syncthreads();
    if (tid == 0) {
        float t = 0.f;
#pragma unroll
        for (int q = 0; q < 8; ++q) t += redb[q];
        gscale = 1.f / fmaxf(sqrtf(t), 1e-12f);
    }
    __syncthreads();
    float gs = gscale;
    for (int idx = tid; idx < Kdim * Cdim; idx += 256) {
        int k = idx >> 7, c = idx & 127;
        out[(size_t)n * (Kdim * Cdim) + idx] = vl[k * 129 + c] * gs;
    }
}

// =====================================================================
extern "C" void kernel_launch(void* const* d_in, const int* in_sizes, int n_in,
                              void* d_out, int out_size) {
    const float* x      = (const float*)d_in[0];
    const float* cent   = (const float*)d_in[2];
    const float* conv_w = (const float*)d_in[3];
    const float* conv_b = (const float*)d_in[4];
    float* out = (float*)d_out;

    cudaFuncSetAttribute(k_logits_mma, cudaFuncAttributeMaxDynamicSharedMemorySize, L_SMEM);

    k_zero<<<16, 256>>>();
    k_logits_mma<<<dim3(16, 64), 256, L_SMEM>>>(x, conv_w, conv_b);
    k_vlad_mma<<<dim3(PSPLIT, 64), 256>>>(x);
    k_final<<<64, 256>>>(cent, out);
}

// round 4
// speedup vs baseline: 2.8264x; 1.2005x over previous
#include <cuda_runtime.h>
#include <cuda_bf16.h>
#include <cstdint>
#include <math.h>

#define Nn 64
#define Cdim 128
#define Pdim 4096
#define Kdim 64
#define PSPLIT 4

// ---- device scratch ----
__device__ __nv_bfloat16 g_a[(size_t)Nn * Kdim * Pdim];      // 32 MB  (a * inv_norm, bf16)
__device__ float g_asum_p[Nn * 16 * Kdim];                    // 256 KB (per-tile asum partials)
__device__ float g_vpart[(size_t)Nn * PSPLIT * Cdim * Kdim];  // 8 MB   [n][ps][c][k]

// ---- mma / ldmatrix wrappers (baseline PTX, sm_80+, valid on sm_103) ----
__device__ __forceinline__ uint32_t smem_u32(const void* p) {
    uint32_t a;
    asm("{ .reg .u64 t; cvta.to.shared.u64 t, %1; cvt.u32.u64 %0, t; }" : "=r"(a) : "l"(p));
    return a;
}
__device__ __forceinline__ void ldsm_x4(uint32_t* r, uint32_t addr) {
    asm volatile("ldmatrix.sync.aligned.m8n8.x4.shared.b16 {%0,%1,%2,%3}, [%4];"
                 : "=r"(r[0]), "=r"(r[1]), "=r"(r[2]), "=r"(r[3]) : "r"(addr));
}
__device__ __forceinline__ void ldsm_x2_trans(uint32_t* r, uint32_t addr) {
    asm volatile("ldmatrix.sync.aligned.m8n8.x2.trans.shared.b16 {%0,%1}, [%2];"
                 : "=r"(r[0]), "=r"(r[1]) : "r"(addr));
}
__device__ __forceinline__ void mma_bf16(float* d, const uint32_t* a, const uint32_t* b) {
    asm volatile(
        "mma.sync.aligned.m16n8k16.row.col.f32.bf16.bf16.f32 "
        "{%0,%1,%2,%3}, {%4,%5,%6,%7}, {%8,%9}, {%0,%1,%2,%3};"
        : "+f"(d[0]), "+f"(d[1]), "+f"(d[2]), "+f"(d[3])
        : "r"(a[0]), "r"(a[1]), "r"(a[2]), "r"(a[3]), "r"(b[0]), "r"(b[1]));
}
__device__ __forceinline__ void split_bf16(float v, __nv_bfloat16& h, __nv_bfloat16& l) {
    h = __float2bfloat16(v);
    l = __float2bfloat16(v - __bfloat162float(h));
}

// =====================================================================
// K_logits_mma: per (n, 256-pixel tile).
//  - stage raw x in 32-channel chunks as bf16 hi/lo; accumulate sumsq per pixel
//  - logits = inv * (W @ x) + b via 3-term bf16 mma split
//  - softmax over 64 clusters; write a*inv (bf16) to g_a; fp32 asum partials.
// =====================================================================
#define L_WN 8704    // 64*136 elems per W plane
#define L_XN 8448    // 32*264 elems per x plane
#define L_SMEM 70144

__global__ __launch_bounds__(256, 2) void k_logits_mma(const float* __restrict__ x,
                                                       const float* __restrict__ conv_w,
                                                       const float* __restrict__ conv_b) {
    extern __shared__ __align__(16) char dsm[];
    __nv_bfloat16* wh = (__nv_bfloat16*)dsm;
    __nv_bfloat16* wl = wh + L_WN;
    __nv_bfloat16* xh = wl + L_WN;
    __nv_bfloat16* xl = xh + L_XN;
    __nv_bfloat16* aout = xh;                  // alias: 64*264 == 2*32*264
    float* s_sumsq = (float*)(xl + L_XN);      // 256
    float* s_asum = s_sumsq + 256;             // 64
    float* s_b = s_asum + 64;                  // 64

    const int n = blockIdx.y;
    const int p0 = blockIdx.x * 256;
    const int tid = threadIdx.x;
    const int w = tid >> 5, lane = tid & 31;
    const int pw = w * 32;

    const uint32_t u_wh = smem_u32(wh), u_wl = smem_u32(wl);
    const uint32_t u_xh = smem_u32(xh), u_xl = smem_u32(xl);

#pragma unroll
    for (int r = 0; r < 8; ++r) {
        int f4 = tid + r * 256;
        int row = f4 >> 5, col4 = f4 & 31;
        float4 v = *(const float4*)(conv_w + row * 128 + col4 * 4);
        __nv_bfloat16 h, l;
        split_bf16(v.x, h, l); wh[row * 136 + col4 * 4 + 0] = h; wl[row * 136 + col4 * 4 + 0] = l;
        split_bf16(v.y, h, l); wh[row * 136 + col4 * 4 + 1] = h; wl[row * 136 + col4 * 4 + 1] = l;
        split_bf16(v.z, h, l); wh[row * 136 + col4 * 4 + 2] = h; wl[row * 136 + col4 * 4 + 2] = l;
        split_bf16(v.w, h, l); wh[row * 136 + col4 * 4 + 3] = h; wl[row * 136 + col4 * 4 + 3] = l;
    }
    if (tid < 64) { s_b[tid] = conv_b[tid]; s_asum[tid] = 0.f; }
    s_sumsq[tid] = 0.f;

    float acc[4][4][4];
#pragma unroll
    for (int a = 0; a < 4; ++a)
#pragma unroll
        for (int b = 0; b < 4; ++b)
#pragma unroll
            for (int c = 0; c < 4; ++c) acc[a][b][c] = 0.f;

    const float* xg = x + (size_t)n * Cdim * Pdim + p0;

    for (int cb = 0; cb < 128; cb += 32) {
        __syncthreads();
#pragma unroll
        for (int r = 0; r < 8; ++r) {
            int f4 = tid + r * 256;
            int row = f4 >> 6, col4 = f4 & 63;
            float4 v = *(const float4*)(xg + (size_t)(cb + row) * Pdim + col4 * 4);
            __nv_bfloat16 h, l;
            split_bf16(v.x, h, l); xh[row * 264 + col4 * 4 + 0] = h; xl[row * 264 + col4 * 4 + 0] = l;
            split_bf16(v.y, h, l); xh[row * 264 + col4 * 4 + 1] = h; xl[row * 264 + col4 * 4 + 1] = l;
            split_bf16(v.z, h, l); xh[row * 264 + col4 * 4 + 2] = h; xl[row * 264 + col4 * 4 + 2] = l;
            split_bf16(v.w, h, l); xh[row * 264 + col4 * 4 + 3] = h; xl[row * 264 + col4 * 4 + 3] = l;
        }
        __syncthreads();
        {
            float ss = 0.f;
#pragma unroll
            for (int c = 0; c < 32; ++c) {
                float v = __bfloat162float(xh[c * 264 + tid]) + __bfloat162float(xl[c * 264 + tid]);
                ss += v * v;
            }
            s_sumsq[tid] += ss;
        }
#pragma unroll
        for (int ks = 0; ks < 2; ++ks) {
            uint32_t bh[4][2], bl[4][2];
#pragma unroll
            for (int nt = 0; nt < 4; ++nt) {
                uint32_t off = (uint32_t)(((ks * 16 + (lane & 15)) * 264 + pw + nt * 8) * 2);
                ldsm_x2_trans(bh[nt], u_xh + off);
                ldsm_x2_trans(bl[nt], u_xl + off);
            }
#pragma unroll
            for (int mt = 0; mt < 4; ++mt) {
                uint32_t ah[4], al[4];
                uint32_t off = (uint32_t)(((mt * 16 + (lane & 15)) * 136 + cb + ks * 16 + (lane >> 4) * 8) * 2);
                ldsm_x4(ah, u_wh + off);
                ldsm_x4(al, u_wl + off);
#pragma unroll
                for (int nt = 0; nt < 4; ++nt) {
                    mma_bf16(acc[mt][nt], ah, bh[nt]);
                    mma_bf16(acc[mt][nt], ah, bl[nt]);
                    mma_bf16(acc[mt][nt], al, bh[nt]);
                }
            }
        }
    }
    __syncthreads();
    s_sumsq[tid] = 1.f / fmaxf(sqrtf(s_sumsq[tid]), 1e-12f);
    __syncthreads();
    float* s_inv = s_sumsq;

    float iv0[4], iv1[4];
#pragma unroll
    for (int nt = 0; nt < 4; ++nt) {
        int c0 = pw + nt * 8 + (lane & 3) * 2;
        iv0[nt] = s_inv[c0];
        iv1[nt] = s_inv[c0 + 1];
    }
    float bb0[4], bb1[4];
#pragma unroll
    for (int mt = 0; mt < 4; ++mt) {
        bb0[mt] = s_b[mt * 16 + (lane >> 2)];
        bb1[mt] = s_b[mt * 16 + (lane >> 2) + 8];
    }
    float l[4][4][4];
#pragma unroll
    for (int mt = 0; mt < 4; ++mt)
#pragma unroll
        for (int nt = 0; nt < 4; ++nt) {
            l[mt][nt][0] = acc[mt][nt][0] * iv0[nt] + bb0[mt];
            l[mt][nt][1] = acc[mt][nt][1] * iv1[nt] + bb0[mt];
            l[mt][nt][2] = acc[mt][nt][2] * iv0[nt] + bb1[mt];
            l[mt][nt][3] = acc[mt][nt][3] * iv1[nt] + bb1[mt];
        }
    float mx0[4], mx1[4];
#pragma unroll
    for (int nt = 0; nt < 4; ++nt) {
        float m0 = -1e30f, m1 = -1e30f;
#pragma unroll
        for (int mt = 0; mt < 4; ++mt) {
            m0 = fmaxf(m0, fmaxf(l[mt][nt][0], l[mt][nt][2]));
            m1 = fmaxf(m1, fmaxf(l[mt][nt][1], l[mt][nt][3]));
        }
#pragma unroll
        for (int s = 4; s < 32; s <<= 1) {
            m0 = fmaxf(m0, __shfl_xor_sync(0xffffffffu, m0, s));
            m1 = fmaxf(m1, __shfl_xor_sync(0xffffffffu, m1, s));
        }
        mx0[nt] = m0; mx1[nt] = m1;
    }
    float sm0[4], sm1[4];
#pragma unroll
    for (int nt = 0; nt < 4; ++nt) {
        float s0 = 0.f, s1 = 0.f;
#pragma unroll
        for (int mt = 0; mt < 4; ++mt) {
            l[mt][nt][0] = __expf(l[mt][nt][0] - mx0[nt]); s0 += l[mt][nt][0];
            l[mt][nt][2] = __expf(l[mt][nt][2] - mx0[nt]); s0 += l[mt][nt][2];
            l[mt][nt][1] = __expf(l[mt][nt][1] - mx1[nt]); s1 += l[mt][nt][1];
            l[mt][nt][3] = __expf(l[mt][nt][3] - mx1[nt]); s1 += l[mt][nt][3];
        }
#pragma unroll
        for (int s = 4; s < 32; s <<= 1) {
            s0 += __shfl_xor_sync(0xffffffffu, s0, s);
            s1 += __shfl_xor_sync(0xffffffffu, s1, s);
        }
        sm0[nt] = 1.f / s0; sm1[nt] = 1.f / s1;
    }
    float srow0[4] = {0, 0, 0, 0}, srow1[4] = {0, 0, 0, 0};
#pragma unroll
    for (int mt = 0; mt < 4; ++mt) {
        int r0 = mt * 16 + (lane >> 2);
#pragma unroll
        for (int nt = 0; nt < 4; ++nt) {
            int c0 = pw + nt * 8 + (lane & 3) * 2;
            float a0 = l[mt][nt][0] * sm0[nt];
            float a1 = l[mt][nt][1] * sm1[nt];
            float a2 = l[mt][nt][2] * sm0[nt];
            float a3 = l[mt][nt][3] * sm1[nt];
            srow0[mt] += a0 + a1;
            srow1[mt] += a2 + a3;
            __nv_bfloat162 t0(__float2bfloat16(a0 * iv0[nt]), __float2bfloat16(a1 * iv1[nt]));
            __nv_bfloat162 t1(__float2bfloat16(a2 * iv0[nt]), __float2bfloat16(a3 * iv1[nt]));
            *(__nv_bfloat162*)&aout[r0 * 264 + c0] = t0;
            *(__nv_bfloat162*)&aout[(r0 + 8) * 264 + c0] = t1;
        }
    }
#pragma unroll
    for (int mt = 0; mt < 4; ++mt) {
        float t0 = srow0[mt], t1 = srow1[mt];
        t0 += __shfl_xor_sync(0xffffffffu, t0, 1); t0 += __shfl_xor_sync(0xffffffffu, t0, 2);
        t1 += __shfl_xor_sync(0xffffffffu, t1, 1); t1 += __shfl_xor_sync(0xffffffffu, t1, 2);
        if ((lane & 3) == 0) {
            atomicAdd(&s_asum[mt * 16 + (lane >> 2)], t0);
            atomicAdd(&s_asum[mt * 16 + (lane >> 2) + 8], t1);
        }
    }
    __syncthreads();
    __nv_bfloat16* ga = g_a + (size_t)(n * Kdim) * Pdim + p0;
#pragma unroll
    for (int r = 0; r < 8; ++r) {
        int f = tid + r * 256;
        int row = f >> 5, seg = f & 31;
        *(uint4*)(ga + (size_t)row * Pdim + seg * 8) = *(uint4*)&aout[row * 264 + seg * 8];
    }
    if (tid < 64) g_asum_p[(n * 16 + blockIdx.x) * Kdim + tid] = s_asum[tid];
}

// =====================================================================
// K_vlad_mma: single-term bf16 x (raw), bf16 a'. Register-prefetch pipeline.
// vpart[n][ps][c][k] = sum_{p in split} x[c,p] * a'[k,p]
// =====================================================================
__global__ __launch_bounds__(256, 2) void k_vlad_mma(const float* __restrict__ x) {
    __shared__ __align__(16) __nv_bfloat16 xh[128 * 72];
    __shared__ __align__(16) __nv_bfloat16 as_[64 * 72];

    const int n = blockIdx.y, ps = blockIdx.x;
    const int tid = threadIdx.x;
    const int w = tid >> 5, lane = tid & 31;
    const int pb0 = ps * (Pdim / PSPLIT);

    const uint32_t u_xh = smem_u32(xh), u_as = smem_u32(as_);

    float acc[8][4];
#pragma unroll
    for (int a = 0; a < 8; ++a)
#pragma unroll
        for (int b = 0; b < 4; ++b) acc[a][b] = 0.f;

    const float* xg = x + (size_t)n * Cdim * Pdim;
    const __nv_bfloat16* ga = g_a + (size_t)(n * Kdim) * Pdim;

    const int xrow = tid >> 4, xcol4 = tid & 15;    // x: 16 rows per pass, 8 passes
    const int arow = tid >> 3, aseg = tid & 7;      // a: 32 rows per pass, 2 passes

    float4 vx[8];
    uint4 va[2];
    // prefetch chunk 0
#pragma unroll
    for (int r = 0; r < 8; ++r)
        vx[r] = *(const float4*)(xg + (size_t)(xrow + r * 16) * Pdim + pb0 + xcol4 * 4);
#pragma unroll
    for (int r = 0; r < 2; ++r)
        va[r] = *(const uint4*)(ga + (size_t)(arow + r * 32) * Pdim + pb0 + aseg * 8);

    for (int pc = 0; pc < 16; ++pc) {
        // store staged regs -> smem (x converted to bf16)
#pragma unroll
        for (int r = 0; r < 8; ++r) {
            __nv_bfloat162 h01(__float2bfloat16(vx[r].x), __float2bfloat16(vx[r].y));
            __nv_bfloat162 h23(__float2bfloat16(vx[r].z), __float2bfloat16(vx[r].w));
            *(__nv_bfloat162*)&xh[(xrow + r * 16) * 72 + xcol4 * 4] = h01;
            *(__nv_bfloat162*)&xh[(xrow + r * 16) * 72 + xcol4 * 4 + 2] = h23;
        }
#pragma unroll
        for (int r = 0; r < 2; ++r)
            *(uint4*)&as_[(arow + r * 32) * 72 + aseg * 8] = va[r];
        __syncthreads();

        // issue prefetch of next chunk (overlaps with mma below)
        if (pc < 15) {
            const int pb = pb0 + (pc + 1) * 64;
#pragma unroll
            for (int r = 0; r < 8; ++r)
                vx[r] = *(const float4*)(xg + (size_t)(xrow + r * 16) * Pdim + pb + xcol4 * 4);
#pragma unroll
            for (int r = 0; r < 2; ++r)
                va[r] = *(const uint4*)(ga + (size_t)(arow + r * 32) * Pdim + pb + aseg * 8);
        }

#pragma unroll
        for (int ks = 0; ks < 4; ++ks) {
            uint32_t ah[4];
            uint32_t offA = (uint32_t)(((w * 16 + (lane & 15)) * 72 + ks * 16 + (lane >> 4) * 8) * 2);
            ldsm_x4(ah, u_xh + offA);
#pragma unroll
            for (int ntp = 0; ntp < 4; ++ntp) {
                uint32_t b4[4];
                int row = ntp * 16 + ((lane >> 4) << 3) + (lane & 7);
                int col = ks * 16 + ((lane >> 3) & 1) * 8;
                ldsm_x4(b4, u_as + (uint32_t)((row * 72 + col) * 2));
                mma_bf16(acc[2 * ntp], ah, b4);
                mma_bf16(acc[2 * ntp + 1], ah, b4 + 2);
            }
        }
        __syncthreads();
    }
    float* vp = g_vpart + (size_t)(n * PSPLIT + ps) * (Cdim * Kdim);
    int r0 = w * 16 + (lane >> 2);
    int c0 = (lane & 3) * 2;
#pragma unroll
    for (int nt = 0; nt < 8; ++nt) {
        float2 t0 = make_float2(acc[nt][0], acc[nt][1]);
        float2 t1 = make_float2(acc[nt][2], acc[nt][3]);
        *(float2*)&vp[(size_t)r0 * Kdim + nt * 8 + c0] = t0;
        *(float2*)&vp[(size_t)(r0 + 8) * Kdim + nt * 8 + c0] = t1;
    }
}

// =====================================================================
// K_final: 1024 threads. Reduce asum partials + vlad partials, subtract,
// intra-norm per k row, global norm, write out.
// =====================================================================
__global__ __launch_bounds__(1024) void k_final(const float* __restrict__ cent,
                                                float* __restrict__ out) {
    const int n = blockIdx.x;
    const int tid = threadIdx.x;
    __shared__ float vl[Kdim * 129];
    __shared__ float rn[Kdim];
    __shared__ float redb[32];
    __shared__ float s_asum[64];
    __shared__ float gscale;

    if (tid < 64) {
        float s = 0.f;
#pragma unroll
        for (int t = 0; t < 16; ++t) s += g_asum_p[(n * 16 + t) * Kdim + tid];
        s_asum[tid] = s;
    }
    __syncthreads();

    const float* vp = g_vpart + (size_t)(n * PSPLIT) * (Cdim * Kdim);
#pragma unroll
    for (int it = 0; it < 2; ++it) {
        int i4 = tid + it * 1024;
        int idx = i4 * 4;
        float4 s = *(const float4*)(vp + idx);
        float4 s1 = *(const float4*)(vp + (Cdim * Kdim) + idx);
        float4 s2 = *(const float4*)(vp + 2 * (Cdim * Kdim) + idx);
        float4 s3 = *(const float4*)(vp + 3 * (Cdim * Kdim) + idx);
        s.x += s1.x + s2.x + s3.x;
        s.y += s1.y + s2.y + s3.y;
        s.z += s1.z + s2.z + s3.z;
        s.w += s1.w + s2.w + s3.w;
        int c = idx >> 6, k = idx & 63;
        vl[(k + 0) * 129 + c] = s.x - s_asum[k + 0] * cent[(k + 0) * Cdim + c];
        vl[(k + 1) * 129 + c] = s.y - s_asum[k + 1] * cent[(k + 1) * Cdim + c];
        vl[(k + 2) * 129 + c] = s.z - s_asum[k + 2] * cent[(k + 2) * Cdim + c];
        vl[(k + 3) * 129 + c] = s.w - s_asum[k + 3] * cent[(k + 3) * Cdim + c];
    }
    __syncthreads();

    int w = tid >> 5, lane = tid & 31;
#pragma unroll
    for (int kk = 0; kk < 2; ++kk) {
        int k = w * 2 + kk;
        float t = 0.f;
#pragma unroll
        for (int m = 0; m < 4; ++m) {
            float v = vl[k * 129 + lane + m * 32];
            t += v * v;
        }
#pragma unroll
        for (int off = 16; off > 0; off >>= 1) t += __shfl_xor_sync(0xffffffffu, t, off);
        if (lane == 0) rn[k] = 1.f / fmaxf(sqrtf(t), 1e-12f);
    }
    __syncthreads();

    float tot = 0.f;
#pragma unroll
    for (int it = 0; it < 8; ++it) {
        int idx = tid + it * 1024;
        int k = idx >> 7, c = idx & 127;
        float v = vl[k * 129 + c] * rn[k];
        vl[k * 129 + c] = v;
        tot += v * v;
    }
#pragma unroll
    for (int off = 16; off > 0; off >>= 1) tot += __shfl_xor_sync(0xffffffffu, tot, off);
    if (lane == 0) redb[w] = tot;
    __syncthreads();
    if (tid == 0) {
        float t = 0.f;
#pragma unroll
        for (int q = 0; q < 32; ++q) t += redb[q];
        gscale = 1.f / fmaxf(sqrtf(t), 1e-12f);
    }
    __syncthreads();
    float gs = gscale;
#pragma unroll
    for (int it = 0; it < 8; ++it) {
        int idx = tid + it * 1024;
        int k = idx >> 7, c = idx & 127;
        out[(size_t)n * (Kdim * Cdim) + idx] = vl[k * 129 + c] * gs;
    }
}

// =====================================================================
extern "C" void kernel_launch(void* const* d_in, const int* in_sizes, int n_in,
                              void* d_out, int out_size) {
    const float* x      = (const float*)d_in[0];
    const float* cent   = (const float*)d_in[2];
    const float* conv_w = (const float*)d_in[3];
    const float* conv_b = (const float*)d_in[4];
    float* out = (float*)d_out;

    cudaFuncSetAttribute(k_logits_mma, cudaFuncAttributeMaxDynamicSharedMemorySize, L_SMEM);

    k_logits_mma<<<dim3(16, 64), 256, L_SMEM>>>(x, conv_w, conv_b);
    k_vlad_mma<<<dim3(PSPLIT, 64), 256>>>(x);
    k_final<<<64, 1024>>>(cent, out);
}